// round 4
// baseline (speedup 1.0000x reference)
#include <cuda_runtime.h>
#include <cstdint>

// ---------------------------------------------------------------------------
// 4-layer GCN:
//   per layer: h = (x * out_norm[:,None]) @ W ; agg = seg_sum(h[src], dst)
//              out = agg * in_norm[:,None] + b ; relu (layers 0..2)
// Strategy: device-side dtype probe for edge_index (JAX x64-off silently makes
// int32 despite jnp.int64), normalize to int32 src/dst, build dst-CSR once
// per launch, then per layer: scaled SGEMM + CSR gather-aggregate (no float
// atomics).
// ---------------------------------------------------------------------------

#define NN 50000
#define NE 800000

// scratch (device globals: no allocation allowed)
__device__ float g_bufA[NN * 128];
__device__ float g_bufB[NN * 128];
__device__ float g_out_norm[NN];
__device__ float g_in_norm[NN];
__device__ int   g_out_deg[NN];
__device__ int   g_in_deg[NN];
__device__ int   g_cursor[NN];
__device__ int   g_row_ptr[NN + 1];
__device__ int   g_col_idx[NE];
__device__ int   g_src[NE];
__device__ int   g_dst[NE];
__device__ int   g_is64;

// ------------------------- edge dtype probe + convert ----------------------

// int64 node ids < 2^31 have zero high words at odd 32-bit positions; random
// int32 ids at those positions are ~never all zero across 64 samples.
__global__ void detect_dtype_kernel(const int* __restrict__ w) {
    if (threadIdx.x == 0 && blockIdx.x == 0) {
        int nz = 0;
        for (int i = 0; i < 64; i++)
            if (w[2 * i + 1] != 0) nz = 1;
        g_is64 = (nz == 0) ? 1 : 0;
    }
}

__global__ void convert_edges_kernel(const void* __restrict__ ei, int e) {
    int i = blockIdx.x * blockDim.x + threadIdx.x;
    if (i >= e) return;
    if (g_is64) {
        const long long* p = (const long long*)ei;
        g_src[i] = (int)p[i];
        g_dst[i] = (int)p[e + i];
    } else {
        const int* p = (const int*)ei;
        g_src[i] = p[i];
        g_dst[i] = p[e + i];
    }
}

// -------------------------------- setup -----------------------------------

__global__ void init_counts_kernel(int n) {
    int i = blockIdx.x * blockDim.x + threadIdx.x;
    if (i < n) {
        g_out_deg[i] = 0;
        g_in_deg[i]  = 0;
        g_cursor[i]  = 0;
    }
}

__global__ void histogram_kernel(int e) {
    int i = blockIdx.x * blockDim.x + threadIdx.x;
    if (i < e) {
        atomicAdd(&g_out_deg[g_src[i]], 1);
        atomicAdd(&g_in_deg[g_dst[i]], 1);
    }
}

__global__ void norms_kernel(int n) {
    int i = blockIdx.x * blockDim.x + threadIdx.x;
    if (i < n) {
        g_out_norm[i] = rsqrtf((float)max(g_out_deg[i], 1));
        g_in_norm[i]  = rsqrtf((float)max(g_in_deg[i], 1));
    }
}

// single-block exclusive scan of g_in_deg -> g_row_ptr
__global__ void scan_kernel(int n) {
    __shared__ int sums[1024];
    const int tid = threadIdx.x;
    const int per = (n + 1023) / 1024;
    const int start = tid * per;
    const int stop  = min(start + per, n);

    int s = 0;
    for (int i = start; i < stop; ++i) s += g_in_deg[i];
    sums[tid] = s;
    __syncthreads();

    // Hillis-Steele inclusive scan over 1024 partials
    for (int off = 1; off < 1024; off <<= 1) {
        int v = 0;
        if (tid >= off) v = sums[tid - off];
        __syncthreads();
        sums[tid] += v;
        __syncthreads();
    }

    int run = (tid == 0) ? 0 : sums[tid - 1];  // exclusive prefix
    for (int i = start; i < stop; ++i) {
        g_row_ptr[i] = run;
        run += g_in_deg[i];
    }
    if (tid == 1023) g_row_ptr[n] = sums[1023];  // total
}

__global__ void fill_csr_kernel(int e) {
    int i = blockIdx.x * blockDim.x + threadIdx.x;
    if (i < e) {
        int d = g_dst[i];
        int pos = g_row_ptr[d] + atomicAdd(&g_cursor[d], 1);
        g_col_idx[pos] = g_src[i];
    }
}

// ------------------------------ scaled GEMM --------------------------------
// C[n, FOUT] = (X[n, FIN] * out_norm[:,None]) @ W[FIN, FOUT]
// BM=64, BK=32, 256 threads (16x16), each thread: 4 x (FOUT/16) outputs.

template <int FIN, int FOUT>
__global__ __launch_bounds__(256) void gemm_scaled_kernel(
    const float* __restrict__ X, const float* __restrict__ W,
    float* __restrict__ C, int n)
{
    constexpr int BM = 64;
    constexpr int BK = 32;
    constexpr int TN = FOUT / 16;  // 8 for FOUT=128, 4 for FOUT=64

    __shared__ float As[BM][BK + 1];
    __shared__ float Ws[BK][FOUT];

    const int tid = threadIdx.x;
    const int tx = tid & 15;
    const int ty = tid >> 4;
    const int row0 = blockIdx.x * BM;

    float acc[4][TN];
#pragma unroll
    for (int i = 0; i < 4; i++)
#pragma unroll
        for (int j = 0; j < TN; j++) acc[i][j] = 0.0f;

    for (int k0 = 0; k0 < FIN; k0 += BK) {
        // load A tile, scaled by out_norm (coalesced over k)
#pragma unroll
        for (int idx = tid; idx < BM * BK; idx += 256) {
            int r = idx / BK, k = idx % BK;
            int gr = row0 + r;
            As[r][k] = (gr < n)
                ? X[(size_t)gr * FIN + k0 + k] * g_out_norm[gr]
                : 0.0f;
        }
        // load W tile (coalesced over cols)
#pragma unroll
        for (int idx = tid; idx < BK * FOUT; idx += 256) {
            int k = idx / FOUT, c = idx % FOUT;
            Ws[k][c] = W[(size_t)(k0 + k) * FOUT + c];
        }
        __syncthreads();

#pragma unroll
        for (int kk = 0; kk < BK; kk++) {
            float a[4], b[TN];
#pragma unroll
            for (int i = 0; i < 4; i++) a[i] = As[ty + i * 16][kk];
#pragma unroll
            for (int j = 0; j < TN; j++) b[j] = Ws[kk][tx + j * 16];
#pragma unroll
            for (int i = 0; i < 4; i++)
#pragma unroll
                for (int j = 0; j < TN; j++) acc[i][j] += a[i] * b[j];
        }
        __syncthreads();
    }

#pragma unroll
    for (int i = 0; i < 4; i++) {
        int gr = row0 + ty + i * 16;
        if (gr < n) {
#pragma unroll
            for (int j = 0; j < TN; j++)
                C[(size_t)gr * FOUT + tx + j * 16] = acc[i][j];
        }
    }
}

// --------------------------- CSR aggregate ---------------------------------
// out[v, f] = maybe_relu( in_norm[v] * sum_{e in row v} H[col_idx[e], f] + b[f] )
// One block per node, F threads; gathers are coalesced 4B*F per edge.

template <int F, bool RELU>
__global__ void aggregate_kernel(const float* __restrict__ H,
                                 const float* __restrict__ bias,
                                 float* __restrict__ out, int n)
{
    const int v = blockIdx.x;
    const int f = threadIdx.x;
    if (v >= n) return;

    const int beg = g_row_ptr[v];
    const int end = g_row_ptr[v + 1];

    float acc = 0.0f;
    for (int e = beg; e < end; ++e) {
        int s = g_col_idx[e];
        acc += __ldg(&H[(size_t)s * F + f]);
    }

    float r = acc * g_in_norm[v] + bias[f];
    if (RELU) r = fmaxf(r, 0.0f);
    out[(size_t)v * F + f] = r;
}

// ------------------------------- launch ------------------------------------

extern "C" void kernel_launch(void* const* d_in, const int* in_sizes, int n_in,
                              void* d_out, int out_size)
{
    const float* x  = (const float*)d_in[0];
    const void*  ei = (const void*)d_in[1];
    const float* W0 = (const float*)d_in[2];
    const float* b0 = (const float*)d_in[3];
    const float* W1 = (const float*)d_in[4];
    const float* b1 = (const float*)d_in[5];
    const float* W2 = (const float*)d_in[6];
    const float* b2 = (const float*)d_in[7];
    const float* W3 = (const float*)d_in[8];
    const float* b3 = (const float*)d_in[9];
    float* out = (float*)d_out;

    const int e = in_sizes[1] / 2;        // 800000 edges
    const int n = in_sizes[0] / 256;      // 50000 nodes

    void* pA = nullptr;
    void* pB = nullptr;
    cudaGetSymbolAddress(&pA, g_bufA);
    cudaGetSymbolAddress(&pB, g_bufB);
    float* bufA = (float*)pA;
    float* bufB = (float*)pB;

    const int TB = 256;
    const int eg = (e + TB - 1) / TB;
    const int ng = (n + TB - 1) / TB;

    // normalize edge dtype (int32 vs int64) into g_src/g_dst
    detect_dtype_kernel<<<1, 32>>>((const int*)ei);
    convert_edges_kernel<<<eg, TB>>>(ei, e);

    // CSR + norms
    init_counts_kernel<<<ng, TB>>>(n);
    histogram_kernel<<<eg, TB>>>(e);
    norms_kernel<<<ng, TB>>>(n);
    scan_kernel<<<1, 1024>>>(n);
    fill_csr_kernel<<<eg, TB>>>(e);

    const int gemm_grid = (n + 63) / 64;

    // layer 0: 256 -> 128, relu
    gemm_scaled_kernel<256, 128><<<gemm_grid, 256>>>(x, W0, bufA, n);
    aggregate_kernel<128, true><<<n, 128>>>(bufA, b0, bufB, n);

    // layer 1: 128 -> 128, relu
    gemm_scaled_kernel<128, 128><<<gemm_grid, 256>>>(bufB, W1, bufA, n);
    aggregate_kernel<128, true><<<n, 128>>>(bufA, b1, bufB, n);

    // layer 2: 128 -> 128, relu
    gemm_scaled_kernel<128, 128><<<gemm_grid, 256>>>(bufB, W2, bufA, n);
    aggregate_kernel<128, true><<<n, 128>>>(bufA, b2, bufB, n);

    // layer 3: 128 -> 64, no relu, write to d_out
    gemm_scaled_kernel<128, 64><<<gemm_grid, 256>>>(bufB, W3, bufA, n);
    aggregate_kernel<64, false><<<n, 64>>>(bufA, b3, out, n);
}

// round 6
// speedup vs baseline: 1.9384x; 1.9384x over previous
#include <cuda_runtime.h>
#include <cuda_bf16.h>
#include <cstdint>

// ---------------------------------------------------------------------------
// 4-layer GCN. tcgen05 is rejected by this toolchain (PTX targets compute_103,
// not 103a), so GEMM uses baseline mma.sync.m16n8k16 bf16 with split-precision
// (3 products: hi*hi + hi*lo + lo*hi, fp32 register accumulators).
// CSR build: fused convert+histogram, multi-block scan, cursor fill.
// Aggregation: CSR gather, warp-per-node float4.
// ---------------------------------------------------------------------------

#define NN 50000
#define NE 800000
#define SCAN_T 256
#define SCAN_G ((NN + SCAN_T - 1) / SCAN_T)   // 196

// scratch (device globals: no allocation allowed)
__device__ float g_bufA[NN * 128];
__device__ float g_bufB[NN * 128];
__device__ float g_out_norm[NN];
__device__ float g_in_norm[NN];
__device__ int   g_out_deg[NN];
__device__ int   g_in_deg[NN];
__device__ int   g_cursor[NN];
__device__ int   g_row_ptr[NN + 1];
__device__ int   g_col_idx[NE];
__device__ int   g_src[NE];
__device__ int   g_dst[NE];
__device__ int   g_bsum[SCAN_G];
__device__ int   g_is64;

// ============================ PTX helpers ===================================

__device__ __forceinline__ uint32_t smem_u32(const void* p) {
    uint32_t a;
    asm("{ .reg .u64 t; cvta.to.shared.u64 t, %1; cvt.u32.u64 %0, t; }"
        : "=r"(a) : "l"(p));
    return a;
}

__device__ __forceinline__ void ldsm_x4(uint32_t* r, uint32_t addr) {
    asm volatile("ldmatrix.sync.aligned.m8n8.x4.shared.b16 {%0,%1,%2,%3}, [%4];"
                 : "=r"(r[0]), "=r"(r[1]), "=r"(r[2]), "=r"(r[3]) : "r"(addr));
}

__device__ __forceinline__ void ldsm_x4_t(uint32_t* r, uint32_t addr) {
    asm volatile("ldmatrix.sync.aligned.m8n8.x4.trans.shared.b16 {%0,%1,%2,%3}, [%4];"
                 : "=r"(r[0]), "=r"(r[1]), "=r"(r[2]), "=r"(r[3]) : "r"(addr));
}

__device__ __forceinline__ void mma_bf16(float* c, const uint32_t* a,
                                         uint32_t b0, uint32_t b1) {
    asm volatile(
        "mma.sync.aligned.m16n8k16.row.col.f32.bf16.bf16.f32 "
        "{%0,%1,%2,%3}, {%4,%5,%6,%7}, {%8,%9}, {%0,%1,%2,%3};"
        : "+f"(c[0]), "+f"(c[1]), "+f"(c[2]), "+f"(c[3])
        : "r"(a[0]), "r"(a[1]), "r"(a[2]), "r"(a[3]), "r"(b0), "r"(b1));
}

// ==================== edge dtype probe + fused convert/hist =================

__global__ void detect_dtype_kernel(const int* __restrict__ w) {
    if (threadIdx.x == 0 && blockIdx.x == 0) {
        int nz = 0;
        for (int i = 0; i < 64; i++)
            if (w[2 * i + 1] != 0) nz = 1;
        g_is64 = (nz == 0) ? 1 : 0;
    }
}

__global__ void init_counts_kernel(int n) {
    int i = blockIdx.x * blockDim.x + threadIdx.x;
    if (i < n) {
        g_out_deg[i] = 0;
        g_in_deg[i]  = 0;
        g_cursor[i]  = 0;
    }
}

__global__ void conv_hist_kernel(const void* __restrict__ ei, int e) {
    int i = blockIdx.x * blockDim.x + threadIdx.x;
    if (i >= e) return;
    int s, d;
    if (g_is64) {
        const long long* p = (const long long*)ei;
        s = (int)p[i];
        d = (int)p[e + i];
    } else {
        const int* p = (const int*)ei;
        s = p[i];
        d = p[e + i];
    }
    g_src[i] = s;
    g_dst[i] = d;
    atomicAdd(&g_out_deg[s], 1);
    atomicAdd(&g_in_deg[d], 1);
}

__global__ void norms_kernel(int n) {
    int i = blockIdx.x * blockDim.x + threadIdx.x;
    if (i < n) {
        g_out_norm[i] = rsqrtf((float)max(g_out_deg[i], 1));
        g_in_norm[i]  = rsqrtf((float)max(g_in_deg[i], 1));
    }
}

// ------------------------- multi-block exclusive scan -----------------------

__global__ void scan_bsum_kernel(int n) {
    __shared__ int sh[SCAN_T];
    int tid = threadIdx.x;
    int i = blockIdx.x * SCAN_T + tid;
    sh[tid] = (i < n) ? g_in_deg[i] : 0;
    __syncthreads();
    for (int off = 128; off > 0; off >>= 1) {
        if (tid < off) sh[tid] += sh[tid + off];
        __syncthreads();
    }
    if (tid == 0) g_bsum[blockIdx.x] = sh[0];
}

__global__ void scan_top_kernel() {
    __shared__ int sh[SCAN_G];
    int tid = threadIdx.x;
    if (tid < SCAN_G) sh[tid] = g_bsum[tid];
    __syncthreads();
    if (tid == 0) {
        int run = 0;
        for (int b = 0; b < SCAN_G; b++) {
            int v = sh[b];
            g_bsum[b] = run;
            run += v;
        }
    }
}

__global__ void scan_fill_kernel(int n) {
    __shared__ int sh[SCAN_T];
    int tid = threadIdx.x;
    int i = blockIdx.x * SCAN_T + tid;
    int d = (i < n) ? g_in_deg[i] : 0;
    sh[tid] = d;
    __syncthreads();
    for (int off = 1; off < SCAN_T; off <<= 1) {
        int v = (tid >= off) ? sh[tid - off] : 0;
        __syncthreads();
        sh[tid] += v;
        __syncthreads();
    }
    if (i < n) {
        int incl = sh[tid];
        g_row_ptr[i] = g_bsum[blockIdx.x] + incl - d;
        if (i == n - 1) g_row_ptr[n] = g_bsum[blockIdx.x] + incl;
    }
}

__global__ void fill_csr_kernel(int e) {
    int i = blockIdx.x * blockDim.x + threadIdx.x;
    if (i < e) {
        int d = g_dst[i];
        int pos = g_row_ptr[d] + atomicAdd(&g_cursor[d], 1);
        g_col_idx[pos] = g_src[i];
    }
}

// ================== bf16 split-precision mma.sync GEMM ======================
// C[n,FOUT] = (X[n,FIN] * out_norm[:,None]) @ W[FIN,FOUT], fp32 out.
// BM=128 rows/CTA, K chunked by 64. 8 warps: 4(m) x 2(n); warp = 32 x FOUT/2.
// smem: A (hi,lo) [128][64] bf16 rows padded to 144B; B (hi,lo) [64][FOUT]
// bf16 rows padded to FOUT*2+16 B. Both padded strides are odd multiples of
// 16B -> conflict-free ldmatrix.

union BF4 {
    unsigned long long u64;
    __nv_bfloat16 b[4];
};

template <int FIN, int FOUT>
__global__ __launch_bounds__(256, 1) void gemm_mma_kernel(
    const float* __restrict__ X, const float* __restrict__ W,
    float* __restrict__ C, int n)
{
    constexpr int BK = 64;
    constexpr int NCHUNK = FIN / BK;
    constexpr int RS_A = BK * 2 + 16;          // 144 B
    constexpr int RS_B = FOUT * 2 + 16;        // 272 or 144 B
    constexpr int A_SZ = 128 * RS_A;           // 18432
    constexpr int B_SZ = BK * RS_B;            // 17408 or 9216
    constexpr int SM_A_HI = 0;
    constexpr int SM_A_LO = A_SZ;
    constexpr int SM_B_HI = 2 * A_SZ;
    constexpr int SM_B_LO = 2 * A_SZ + B_SZ;
    constexpr int WN = FOUT / 2;               // warp n-extent: 64 or 32
    constexpr int NT = WN / 16;                // x4.trans units: 4 or 2

    extern __shared__ char smem[];
    const uint32_t sb = smem_u32(smem);
    const int tid  = threadIdx.x;
    const int wid  = tid >> 5;
    const int lane = tid & 31;
    const int wm   = wid & 3;                  // m block (32 rows)
    const int wn   = wid >> 2;                 // n block (WN cols)
    const int row0 = blockIdx.x * 128;

    float acc[2][NT * 2][4];
#pragma unroll
    for (int mi = 0; mi < 2; mi++)
#pragma unroll
        for (int t = 0; t < NT * 2; t++)
#pragma unroll
            for (int j = 0; j < 4; j++) acc[mi][t][j] = 0.0f;

    for (int c = 0; c < NCHUNK; ++c) {
        const int k0 = c * BK;

        // ---- load A chunk: 128 rows x 64 k, scale by out_norm, split hi/lo
        for (int idx = tid; idx < 128 * (BK / 4); idx += 256) {
            const int r  = idx >> 4;           // 0..127
            const int k  = (idx & 15) * 4;     // 0..60
            const int gr = row0 + r;
            float4 xv = make_float4(0.f, 0.f, 0.f, 0.f);
            float s = 0.f;
            if (gr < n) {
                xv = __ldg((const float4*)(X + (size_t)gr * FIN + k0 + k));
                s = g_out_norm[gr];
            }
            float v[4] = { xv.x * s, xv.y * s, xv.z * s, xv.w * s };
            BF4 hi, lo;
#pragma unroll
            for (int j = 0; j < 4; j++) {
                __nv_bfloat16 h = __float2bfloat16_rn(v[j]);
                hi.b[j] = h;
                lo.b[j] = __float2bfloat16_rn(v[j] - __bfloat162float(h));
            }
            const uint32_t off = (uint32_t)(r * RS_A + k * 2);
            *(unsigned long long*)(smem + SM_A_HI + off) = hi.u64;
            *(unsigned long long*)(smem + SM_A_LO + off) = lo.u64;
        }

        // ---- load B chunk: 64 k-rows x FOUT, split hi/lo
        for (int idx = tid; idx < BK * (FOUT / 4); idx += 256) {
            const int k  = idx / (FOUT / 4);
            const int nn = (idx % (FOUT / 4)) * 4;
            float4 wv = __ldg((const float4*)(W + (size_t)(k0 + k) * FOUT + nn));
            float v[4] = { wv.x, wv.y, wv.z, wv.w };
            BF4 hi, lo;
#pragma unroll
            for (int j = 0; j < 4; j++) {
                __nv_bfloat16 h = __float2bfloat16_rn(v[j]);
                hi.b[j] = h;
                lo.b[j] = __float2bfloat16_rn(v[j] - __bfloat162float(h));
            }
            const uint32_t off = (uint32_t)(k * RS_B + nn * 2);
            *(unsigned long long*)(smem + SM_B_HI + off) = hi.u64;
            *(unsigned long long*)(smem + SM_B_LO + off) = lo.u64;
        }

        __syncthreads();

        // ---- MMA over 4 k-steps of 16
#pragma unroll
        for (int ks = 0; ks < 4; ks++) {
            const int kk = ks * 16;
            uint32_t a_hi[2][4], a_lo[2][4];
#pragma unroll
            for (int mi = 0; mi < 2; mi++) {
                const int r = wm * 32 + mi * 16 + (lane & 15);
                const int col = kk + ((lane >> 4) << 3);
                const uint32_t off = (uint32_t)(r * RS_A + col * 2);
                ldsm_x4(a_hi[mi], sb + SM_A_HI + off);
                ldsm_x4(a_lo[mi], sb + SM_A_LO + off);
            }
#pragma unroll
            for (int nt = 0; nt < NT; nt++) {
                const int k = kk + (lane & 15);
                const int nn = wn * WN + nt * 16 + ((lane >> 4) << 3);
                const uint32_t off = (uint32_t)(k * RS_B + nn * 2);
                uint32_t bh[4], bl[4];
                ldsm_x4_t(bh, sb + SM_B_HI + off);
                ldsm_x4_t(bl, sb + SM_B_LO + off);
#pragma unroll
                for (int mi = 0; mi < 2; mi++) {
                    mma_bf16(acc[mi][nt * 2 + 0], a_hi[mi], bh[0], bh[1]);
                    mma_bf16(acc[mi][nt * 2 + 1], a_hi[mi], bh[2], bh[3]);
                    mma_bf16(acc[mi][nt * 2 + 0], a_hi[mi], bl[0], bl[1]);
                    mma_bf16(acc[mi][nt * 2 + 1], a_hi[mi], bl[2], bl[3]);
                    mma_bf16(acc[mi][nt * 2 + 0], a_lo[mi], bh[0], bh[1]);
                    mma_bf16(acc[mi][nt * 2 + 1], a_lo[mi], bh[2], bh[3]);
                }
            }
        }
        __syncthreads();
    }

    // ---- epilogue: fragment layout c0,c1 -> row g ; c2,c3 -> row g+8
    const int g = lane >> 2;
    const int q = lane & 3;
#pragma unroll
    for (int mi = 0; mi < 2; mi++) {
        const int rbase = row0 + wm * 32 + mi * 16;
#pragma unroll
        for (int t = 0; t < NT * 2; t++) {
            const int col = wn * WN + t * 8 + q * 2;
            const int r0 = rbase + g;
            const int r1 = rbase + g + 8;
            if (r0 < n)
                *(float2*)(C + (size_t)r0 * FOUT + col) =
                    make_float2(acc[mi][t][0], acc[mi][t][1]);
            if (r1 < n)
                *(float2*)(C + (size_t)r1 * FOUT + col) =
                    make_float2(acc[mi][t][2], acc[mi][t][3]);
        }
    }
}

// --------------------------- CSR aggregate ---------------------------------

template <int F, bool RELU>
__global__ void aggregate_kernel(const float4* __restrict__ H4,
                                 const float* __restrict__ bias,
                                 float4* __restrict__ out4, int n)
{
    constexpr int LPN = F / 4;        // lanes per node: 32 or 16
    constexpr int NPB = 128 / LPN;    // nodes per block: 4 or 8
    const int lane = threadIdx.x % LPN;
    const int slot = threadIdx.x / LPN;
    const int v = blockIdx.x * NPB + slot;
    if (v >= n) return;

    const int beg = g_row_ptr[v];
    const int end = g_row_ptr[v + 1];

    float4 acc = make_float4(0.f, 0.f, 0.f, 0.f);
    for (int e = beg; e < end; ++e) {
        const int s = g_col_idx[e];
        float4 h = __ldg(&H4[(size_t)s * LPN + lane]);
        acc.x += h.x; acc.y += h.y; acc.z += h.z; acc.w += h.w;
    }

    const float nm = g_in_norm[v];
    const float4 b = __ldg(&((const float4*)bias)[lane]);
    float4 r = make_float4(acc.x * nm + b.x, acc.y * nm + b.y,
                           acc.z * nm + b.z, acc.w * nm + b.w);
    if (RELU) {
        r.x = fmaxf(r.x, 0.f); r.y = fmaxf(r.y, 0.f);
        r.z = fmaxf(r.z, 0.f); r.w = fmaxf(r.w, 0.f);
    }
    out4[(size_t)v * LPN + lane] = r;
}

// ------------------------------- launch ------------------------------------

extern "C" void kernel_launch(void* const* d_in, const int* in_sizes, int n_in,
                              void* d_out, int out_size)
{
    const float* x  = (const float*)d_in[0];
    const void*  ei = (const void*)d_in[1];
    const float* W0 = (const float*)d_in[2];
    const float* b0 = (const float*)d_in[3];
    const float* W1 = (const float*)d_in[4];
    const float* b1 = (const float*)d_in[5];
    const float* W2 = (const float*)d_in[6];
    const float* b2 = (const float*)d_in[7];
    const float* W3 = (const float*)d_in[8];
    const float* b3 = (const float*)d_in[9];
    float* out = (float*)d_out;

    const int e = in_sizes[1] / 2;        // 800000 edges
    const int n = in_sizes[0] / 256;      // 50000 nodes

    void* pA = nullptr;
    void* pB = nullptr;
    cudaGetSymbolAddress(&pA, g_bufA);
    cudaGetSymbolAddress(&pB, g_bufB);
    float* bufA = (float*)pA;
    float* bufB = (float*)pB;

    // dynamic smem: 2*A_SZ + 2*B_SZ
    const int smem_f128 = 2 * 128 * 144 + 2 * 64 * 272;  // 71680
    const int smem_f64  = 2 * 128 * 144 + 2 * 64 * 144;  // 55296
    cudaFuncSetAttribute(gemm_mma_kernel<256, 128>,
                         cudaFuncAttributeMaxDynamicSharedMemorySize, smem_f128);
    cudaFuncSetAttribute(gemm_mma_kernel<128, 128>,
                         cudaFuncAttributeMaxDynamicSharedMemorySize, smem_f128);
    cudaFuncSetAttribute(gemm_mma_kernel<128, 64>,
                         cudaFuncAttributeMaxDynamicSharedMemorySize, smem_f64);

    const int TB = 256;
    const int eg = (e + TB - 1) / TB;
    const int ng = (n + TB - 1) / TB;

    // edge normalize + CSR + norms
    detect_dtype_kernel<<<1, 32>>>((const int*)ei);
    init_counts_kernel<<<ng, TB>>>(n);
    conv_hist_kernel<<<eg, TB>>>(ei, e);
    norms_kernel<<<ng, TB>>>(n);
    scan_bsum_kernel<<<SCAN_G, SCAN_T>>>(n);
    scan_top_kernel<<<1, SCAN_T>>>();
    scan_fill_kernel<<<SCAN_G, SCAN_T>>>(n);
    fill_csr_kernel<<<eg, TB>>>(e);

    const int GB = (n + 127) / 128;   // 391

    // layer 0: 256 -> 128, relu
    gemm_mma_kernel<256, 128><<<GB, 256, smem_f128>>>(x, W0, bufA, n);
    aggregate_kernel<128, true><<<(n + 3) / 4, 128>>>((const float4*)bufA, b0, (float4*)bufB, n);

    // layer 1: 128 -> 128, relu
    gemm_mma_kernel<128, 128><<<GB, 256, smem_f128>>>(bufB, W1, bufA, n);
    aggregate_kernel<128, true><<<(n + 3) / 4, 128>>>((const float4*)bufA, b1, (float4*)bufB, n);

    // layer 2: 128 -> 128, relu
    gemm_mma_kernel<128, 128><<<GB, 256, smem_f128>>>(bufB, W2, bufA, n);
    aggregate_kernel<128, true><<<(n + 3) / 4, 128>>>((const float4*)bufA, b2, (float4*)bufB, n);

    // layer 3: 128 -> 64, no relu
    gemm_mma_kernel<128, 64><<<GB, 256, smem_f64>>>(bufB, W3, bufA, n);
    aggregate_kernel<64, false><<<(n + 7) / 8, 128>>>((const float4*)bufA, b3, (float4*)out, n);
}